// round 7
// baseline (speedup 1.0000x reference)
#include <cuda_runtime.h>

// Problem shape
#define TT 512
#define II 10
#define HH 32
#define EE 8                 // batch elements per block (= MMA N)
#define CH 16                // timesteps per x chunk
#define NCH (TT / CH)        // 32
#define GSTR 34              // gates row stride in floats (bank skew, 8B-aligned)

typedef unsigned uu;

__device__ __forceinline__ uu tf32r(float f) {
    uu u; asm("cvt.rna.tf32.f32 %0, %1;" : "=r"(u) : "f"(f)); return u;
}
__device__ __forceinline__ float tanha(float x) {
    float r; asm("tanh.approx.f32 %0, %1;" : "=f"(r) : "f"(x)); return r;
}
// D += A(16x8) * B(8x8), tf32 inputs, fp32 accum (accumulate in place)
__device__ __forceinline__ void mma8(float& d0, float& d1, float& d2, float& d3,
                                     uu a0, uu a1, uu a2, uu a3, uu b0, uu b1) {
    asm("mma.sync.aligned.m16n8k8.row.col.f32.tf32.tf32.f32 "
        "{%0,%1,%2,%3},{%4,%5,%6,%7},{%8,%9},{%0,%1,%2,%3};"
        : "+f"(d0), "+f"(d1), "+f"(d2), "+f"(d3)
        : "r"(a0), "r"(a1), "r"(a2), "r"(a3), "r"(b0), "r"(b1));
}
__device__ __forceinline__ unsigned sm32(const void* p) {
    return (unsigned)__cvta_generic_to_shared(p);
}
__device__ __forceinline__ void cp8(unsigned d, const void* s) {
    asm volatile("cp.async.ca.shared.global [%0], [%1], 8;" :: "r"(d), "l"(s));
}

// 128 threads, 8 elements/block, 4 blocks/SM (single wave for 512 CTAs).
// Warp w computes gate w for all 8 elements via tf32 MMA; weights tf32-hi in regs,
// precision recovered on the B side: gates = W_hi * (b_hi + b_lo).
// x is pre-split into MMA-fragment layout once per chunk; h kept in fragment layout.
__global__ void __launch_bounds__(128, 4) lstm_kernel(
    const float* __restrict__ x,     const float* __restrict__ h0,
    const float* __restrict__ c0,    const float* __restrict__ W_ih,
    const float* __restrict__ W_hh,  const float* __restrict__ b_ih,
    const float* __restrict__ b_hh,  const float* __restrict__ W_lin,
    const float* __restrict__ b_lin, float* __restrict__ out)
{
    __shared__ __align__(16) uint4 xfrag_sh[2][CH][2][32];  // 32 KB  {hi,lo,hi,lo}
    __shared__ __align__(16) float xraw_sh[EE * CH * II];   // 5 KB raw staging
    __shared__ __align__(16) uint4 hfrag_sh[4][32];         // 2 KB  h fragments
    __shared__ __align__(16) float gates_sh[HH * GSTR];     // 4.3 KB

    const int tid  = threadIdx.x;
    const int w    = tid >> 5;          // warp = gate (0=i,1=f,2=g,3=o)
    const int lane = tid & 31;
    const int gid  = lane >> 2;         // MMA groupID (0..7) = element
    const int tig  = lane & 3;          // MMA thread-in-group
    const int base = blockIdx.x * EE;

    const float s     = (w == 2) ? 1.0f : 0.5f;
    const float alpha = (w == 2) ? 1.0f : 0.5f;
    const float beta  = (w == 2) ? 0.0f : 0.5f;

    // ---- resident A fragments (tf32-hi) ----
    uu ah[2][4][4];                      // [m-tile][k-chunk][a-reg]
    uu ax[2][2][4];
    float bv[2][2];
    #pragma unroll
    for (int mt = 0; mt < 2; mt++) {
        #pragma unroll
        for (int rg = 0; rg < 4; rg++) {
            int row = 32 * w + 16 * mt + 8 * (rg & 1) + gid;
            #pragma unroll
            for (int kc = 0; kc < 4; kc++)
                ah[mt][kc][rg] = tf32r(W_hh[row * HH + 8 * kc + 4 * (rg >> 1) + tig] * s);
            #pragma unroll
            for (int kc = 0; kc < 2; kc++) {
                int j = 8 * kc + 4 * (rg >> 1) + tig;
                ax[mt][kc][rg] = tf32r((j < II) ? W_ih[row * II + j] * s : 0.0f);
            }
        }
        int r0 = 32 * w + 16 * mt + gid;
        bv[mt][0] = (b_ih[r0]     + b_hh[r0])     * s;
        bv[mt][1] = (b_ih[r0 + 8] + b_hh[r0 + 8]) * s;
    }

    // ---- per-thread state (l, e) and (l+16, e); precomputed smem pointers ----
    const int e = tid & 7;
    const int l = tid >> 3;             // 0..15
    float c_a = c0[(base + e) * HH + l];
    float c_b = c0[(base + e) * HH + l + 16];
    float h_a = h0[(base + e) * HH + l];
    float h_b = h0[(base + e) * HH + l + 16];
    const float wl0 = W_lin[l];
    const float wl1 = W_lin[l + 16];

    const float2* gpA = reinterpret_cast<const float2*>(&gates_sh[l * GSTR + e * 4]);
    const float2* gpB = reinterpret_cast<const float2*>(&gates_sh[(l + 16) * GSTR + e * 4]);
    const int kcA   = l >> 3;
    const int slotA = (l >> 2) & 1;
    const int laneS = e * 4 + (l & 3);
    uint2* hwA = reinterpret_cast<uint2*>(
        reinterpret_cast<char*>(&hfrag_sh[kcA][laneS]) + slotA * 8);
    uint2* hwB = reinterpret_cast<uint2*>(
        reinterpret_cast<char*>(&hfrag_sh[kcA + 2][laneS]) + slotA * 8);

    {   // initial h fragments
        uu p = tf32r(h_a);
        *hwA = make_uint2(p, __float_as_uint(h_a - __uint_as_float(p)));
        uu p2 = tf32r(h_b);
        *hwB = make_uint2(p2, __float_as_uint(h_b - __uint_as_float(p2)));
    }

    #define PREFETCH(chunk)                                                       \
        do {                                                                      \
            for (int p = tid; p < EE * CH * 5; p += 128) {                        \
                int pe = p / (CH * 5);                                            \
                int r2 = p - pe * (CH * 5);                                       \
                int t  = r2 / 5;                                                  \
                int pj = r2 - t * 5;                                              \
                cp8(sm32(&xraw_sh[pe * (CH * II) + t * II + 2 * pj]),             \
                    x + ((size_t)(base + pe) * TT + (chunk) * CH + t) * II + 2 * pj); \
            }                                                                     \
            asm volatile("cp.async.commit_group;");                               \
        } while (0)

    #define SPLIT(fbuf)                                                           \
        do {                                                                      \
            for (int u = tid; u < CH * 2 * 32; u += 128) {                        \
                int t   = u >> 6;                                                 \
                int rem = u & 63;                                                 \
                int q   = rem >> 5;                                               \
                int ln  = rem & 31;                                               \
                int ge  = ln >> 2;                                                \
                int tg  = ln & 3;                                                 \
                int k0 = 8 * q + tg, k1 = k0 + 4;                                 \
                float v0 = (k0 < II) ? xraw_sh[ge * (CH * II) + t * II + k0] : 0.f; \
                float v1 = (k1 < II) ? xraw_sh[ge * (CH * II) + t * II + k1] : 0.f; \
                uu p0 = tf32r(v0), p1 = tf32r(v1);                                \
                xfrag_sh[fbuf][t][q][ln] = make_uint4(                            \
                    p0, __float_as_uint(v0 - __uint_as_float(p0)),                \
                    p1, __float_as_uint(v1 - __uint_as_float(p1)));               \
            }                                                                     \
        } while (0)

    float ca[2][4], cb[2][4];
    #define XACC(xf0, xf1)                                                        \
        do {                                                                      \
            _Pragma("unroll")                                                     \
            for (int mt = 0; mt < 2; mt++) {                                      \
                ca[mt][0] = bv[mt][0]; ca[mt][1] = bv[mt][0];                     \
                ca[mt][2] = bv[mt][1]; ca[mt][3] = bv[mt][1];                     \
                cb[mt][0] = 0.f; cb[mt][1] = 0.f; cb[mt][2] = 0.f; cb[mt][3] = 0.f; \
                mma8(ca[mt][0], ca[mt][1], ca[mt][2], ca[mt][3],                  \
                     ax[mt][0][0], ax[mt][0][1], ax[mt][0][2], ax[mt][0][3],      \
                     (xf0).x, (xf0).z);                                           \
                mma8(ca[mt][0], ca[mt][1], ca[mt][2], ca[mt][3],                  \
                     ax[mt][1][0], ax[mt][1][1], ax[mt][1][2], ax[mt][1][3],      \
                     (xf1).x, (xf1).z);                                           \
                mma8(cb[mt][0], cb[mt][1], cb[mt][2], cb[mt][3],                  \
                     ax[mt][0][0], ax[mt][0][1], ax[mt][0][2], ax[mt][0][3],      \
                     (xf0).y, (xf0).w);                                           \
                mma8(cb[mt][0], cb[mt][1], cb[mt][2], cb[mt][3],                  \
                     ax[mt][1][0], ax[mt][1][1], ax[mt][1][2], ax[mt][1][3],      \
                     (xf1).y, (xf1).w);                                           \
            }                                                                     \
        } while (0)

    // ---- prologue: chunk 0 raw -> split -> first xacc; prefetch chunk 1 ----
    PREFETCH(0);
    asm volatile("cp.async.wait_group 0;");
    __syncthreads();
    SPLIT(0);
    __syncthreads();
    if (NCH > 1) PREFETCH(1);
    {
        uint4 xf0 = xfrag_sh[0][0][0][lane];
        uint4 xf1 = xfrag_sh[0][0][1][lane];
        XACC(xf0, xf1);
    }

    // ---- recurrence ----
    for (int cix = 0; cix < NCH; cix++) {
        const int fb = cix & 1;
        #pragma unroll 1
        for (int tt = 0; tt < CH; tt++) {
            // h fragments (stored by updaters last step; bar2 ordered)
            uint4 hf[4];
            #pragma unroll
            for (int kc = 0; kc < 4; kc++) hf[kc] = hfrag_sh[kc][lane];

            #pragma unroll
            for (int mt = 0; mt < 2; mt++) {
                #pragma unroll
                for (int kc = 0; kc < 4; kc++) {
                    mma8(ca[mt][0], ca[mt][1], ca[mt][2], ca[mt][3],
                         ah[mt][kc][0], ah[mt][kc][1], ah[mt][kc][2], ah[mt][kc][3],
                         hf[kc].x, hf[kc].z);
                    mma8(cb[mt][0], cb[mt][1], cb[mt][2], cb[mt][3],
                         ah[mt][kc][0], ah[mt][kc][1], ah[mt][kc][2], ah[mt][kc][3],
                         hf[kc].y, hf[kc].w);
                }
                float d0 = ca[mt][0] + cb[mt][0];
                float d1 = ca[mt][1] + cb[mt][1];
                float d2 = ca[mt][2] + cb[mt][2];
                float d3 = ca[mt][3] + cb[mt][3];
                float a0v = fmaf(alpha, tanha(d0), beta);
                float a1v = fmaf(alpha, tanha(d1), beta);
                float a2v = fmaf(alpha, tanha(d2), beta);
                float a3v = fmaf(alpha, tanha(d3), beta);
                int row0 = 16 * mt + gid;
                gates_sh[row0 * GSTR + (2 * tig) * 4 + w]       = a0v;
                gates_sh[row0 * GSTR + (2 * tig + 1) * 4 + w]   = a1v;
                gates_sh[(row0 + 8) * GSTR + (2 * tig) * 4 + w]     = a2v;
                gates_sh[(row0 + 8) * GSTR + (2 * tig + 1) * 4 + w] = a3v;
            }
            __syncthreads();   // bar1: gates ready; h reads complete

            // elementwise update (all threads): states (l,e) and (l+16,e)
            {
                float2 gA0 = gpA[0], gA1 = gpA[1];        // {i,f}, {g,o}
                c_a = fmaf(gA0.y, c_a, gA0.x * gA1.x);
                h_a = gA1.y * tanha(c_a);
                uu p = tf32r(h_a);
                *hwA = make_uint2(p, __float_as_uint(h_a - __uint_as_float(p)));
                float2 gB0 = gpB[0], gB1 = gpB[1];
                c_b = fmaf(gB0.y, c_b, gB0.x * gB1.x);
                h_b = gB1.y * tanha(c_b);
                uu p2 = tf32r(h_b);
                *hwB = make_uint2(p2, __float_as_uint(h_b - __uint_as_float(p2)));
            }
            // x-part of NEXT step (independent of new h) fills the bar window
            if (tt + 1 < CH) {
                uint4 xf0 = xfrag_sh[fb][tt + 1][0][lane];
                uint4 xf1 = xfrag_sh[fb][tt + 1][1][lane];
                XACC(xf0, xf1);
            }
            __syncthreads();   // bar2: new h visible
        }

        if (cix + 1 < NCH) {
            asm volatile("cp.async.wait_group 0;");
            __syncthreads();                       // all threads' raw x arrived
            SPLIT((cix + 1) & 1);
            __syncthreads();                       // frag buffer + raw reuse safe
            if (cix + 2 < NCH) PREFETCH(cix + 2);
            uint4 xf0 = xfrag_sh[(cix + 1) & 1][0][0][lane];
            uint4 xf1 = xfrag_sh[(cix + 1) & 1][0][1][lane];
            XACC(xf0, xf1);
        }
    }

    // ---- final linear head ----
    float* scratch = gates_sh;                      // reuse as [EE][16]
    scratch[e * 16 + l] = fmaf(h_a, wl0, h_b * wl1);
    __syncthreads();
    if (tid < EE) {
        float sum = b_lin[0];
        #pragma unroll
        for (int q = 0; q < 16; q++) sum += scratch[tid * 16 + q];
        out[base + tid] = sum;
    }
}

extern "C" void kernel_launch(void* const* d_in, const int* in_sizes, int n_in,
                              void* d_out, int out_size) {
    const float* x     = (const float*)d_in[0];
    const float* h0    = (const float*)d_in[1];
    const float* c0    = (const float*)d_in[2];
    const float* W_ih  = (const float*)d_in[3];
    const float* W_hh  = (const float*)d_in[4];
    const float* b_ih  = (const float*)d_in[5];
    const float* b_hh  = (const float*)d_in[6];
    const float* W_lin = (const float*)d_in[7];
    const float* b_lin = (const float*)d_in[8];
    float* out = (float*)d_out;

    int B = in_sizes[1] / HH;   // 4096
    lstm_kernel<<<B / EE, 128>>>(x, h0, c0, W_ih, W_hh, b_ih, b_hh, W_lin, b_lin, out);
}

// round 10
// speedup vs baseline: 1.2677x; 1.2677x over previous
#include <cuda_runtime.h>

// Problem shape
#define TT 512
#define II 10
#define HH 32
#define EE 8                 // batch elements per block (= MMA N)
#define CH 32                // timesteps per x chunk
#define NCH (TT / CH)        // 16
#define XPAD 16              // padded feature dim (K for x part)
#define ESTR (CH * XPAD + 4) // x elem stride in floats (+4: bank-conflict skew)

typedef unsigned uu;

__device__ __forceinline__ uu tf32r(float f) {
    uu u; asm("cvt.rna.tf32.f32 %0, %1;" : "=r"(u) : "f"(f)); return u;
}
__device__ __forceinline__ float tanha(float x) {
    float r; asm("tanh.approx.f32 %0, %1;" : "=f"(r) : "f"(x)); return r;
}
// D += A(16x8) * B(8x8), tf32 inputs, fp32 accum (accumulate in place)
__device__ __forceinline__ void mma8(float& d0, float& d1, float& d2, float& d3,
                                     uu a0, uu a1, uu a2, uu a3, uu b0, uu b1) {
    asm("mma.sync.aligned.m16n8k8.row.col.f32.tf32.tf32.f32 "
        "{%0,%1,%2,%3},{%4,%5,%6,%7},{%8,%9},{%0,%1,%2,%3};"
        : "+f"(d0), "+f"(d1), "+f"(d2), "+f"(d3)
        : "r"(a0), "r"(a1), "r"(a2), "r"(a3), "r"(b0), "r"(b1));
}
__device__ __forceinline__ unsigned sm32(const void* p) {
    return (unsigned)__cvta_generic_to_shared(p);
}
__device__ __forceinline__ void cp8(unsigned d, const void* s) {
    asm volatile("cp.async.ca.shared.global [%0], [%1], 8;" :: "r"(d), "l"(s));
}

// 128 threads, 8 elements/block, 4 blocks/SM (single wave for 512 CTAs).
// Warp w computes gate w (rows 32w..32w+31) for all 8 elements via tf32 MMA.
// Weights tf32-hi in registers; h compensated on B side (hi+lo); x tf32-hi only
// (x truncation error is per-step independent, no recurrence feedback).
__global__ void __launch_bounds__(128, 4) lstm_kernel(
    const float* __restrict__ x,     const float* __restrict__ h0,
    const float* __restrict__ c0,    const float* __restrict__ W_ih,
    const float* __restrict__ W_hh,  const float* __restrict__ b_ih,
    const float* __restrict__ b_hh,  const float* __restrict__ W_lin,
    const float* __restrict__ b_lin, float* __restrict__ out)
{
    __shared__ __align__(16) float x_sh[2][EE * ESTR];     // ~33 KB
    __shared__ __align__(16) uint4 hfrag_sh[4][32];        // 2 KB: conflict-free frags
    __shared__ __align__(16) float gates_sh[4][HH][EE];    // post-activation

    const int tid  = threadIdx.x;
    const int w    = tid >> 5;          // warp = gate (0=i,1=f,2=g,3=o)
    const int lane = tid & 31;
    const int gid  = lane >> 2;         // MMA groupID (0..7) = element
    const int tig  = lane & 3;          // MMA thread-in-group
    const int base = blockIdx.x * EE;

    const float s     = (w == 2) ? 1.0f : 0.5f;   // sigmoid fold scale
    const float alpha = (w == 2) ? 1.0f : 0.5f;
    const float beta  = (w == 2) ? 0.0f : 0.5f;

    // ---- resident A fragments: W_hh (K=32) and W_ih (K=16 padded), tf32-hi ----
    uu ah[2][4][4];                      // [m-tile][k-chunk][a-reg]
    uu ax[2][2][4];
    float bv[2][2];
    #pragma unroll
    for (int mt = 0; mt < 2; mt++) {
        #pragma unroll
        for (int rg = 0; rg < 4; rg++) {
            int row = 32 * w + 16 * mt + 8 * (rg & 1) + gid;
            #pragma unroll
            for (int kc = 0; kc < 4; kc++)
                ah[mt][kc][rg] = tf32r(W_hh[row * HH + 8 * kc + 4 * (rg >> 1) + tig] * s);
            #pragma unroll
            for (int kc = 0; kc < 2; kc++) {
                int j = 8 * kc + 4 * (rg >> 1) + tig;
                ax[mt][kc][rg] = tf32r((j < II) ? W_ih[row * II + j] * s : 0.0f);
            }
        }
        int r0 = 32 * w + 16 * mt + gid;
        bv[mt][0] = (b_ih[r0]     + b_hh[r0])     * s;
        bv[mt][1] = (b_ih[r0 + 8] + b_hh[r0 + 8]) * s;
    }

    // ---- per-thread state (l, e) and (l+16, e) ----
    const int e = tid & 7;
    const int l = tid >> 3;             // 0..15
    float c_a = c0[(base + e) * HH + l];
    float c_b = c0[(base + e) * HH + l + 16];
    float h_a = h0[(base + e) * HH + l];
    float h_b = h0[(base + e) * HH + l + 16];
    const float wl0 = W_lin[l];
    const float wl1 = W_lin[l + 16];

    // h fragment write pointers: value k lives in hfrag_sh[k>>3][e*4 + (k&3)],
    // 8-byte slot ((k&7)>>2). h_a has k=l, h_b has k=l+16.
    const int kcA   = l >> 3;           // 0..1
    const int slotA = (l >> 2) & 1;
    const int laneS = e * 4 + (l & 3);
    uint2* hwA = reinterpret_cast<uint2*>(
        reinterpret_cast<char*>(&hfrag_sh[kcA][laneS]) + slotA * 8);
    uint2* hwB = reinterpret_cast<uint2*>(
        reinterpret_cast<char*>(&hfrag_sh[kcA + 2][laneS]) + slotA * 8);

    {   // initial h fragments
        uu p = tf32r(h_a);
        *hwA = make_uint2(p, __float_as_uint(h_a - __uint_as_float(p)));
        uu p2 = tf32r(h_b);
        *hwB = make_uint2(p2, __float_as_uint(h_b - __uint_as_float(p2)));
    }

    // ---- x prefetch ----
    #define PREFETCH(chunk, buf)                                                  \
        do {                                                                      \
            for (int p = tid; p < EE * CH * 5; p += 128) {                        \
                int pe = p / (CH * 5);                                            \
                int r2 = p - pe * (CH * 5);                                       \
                int t  = r2 / 5;                                                  \
                int pj = r2 - t * 5;                                              \
                const float* src = x + ((size_t)(base + pe) * TT +                \
                                        (chunk) * CH + t) * II + 2 * pj;          \
                cp8(sm32(&x_sh[buf][pe * ESTR + t * XPAD + 2 * pj]), src);        \
            }                                                                     \
            asm volatile("cp.async.commit_group;");                               \
        } while (0)

    PREFETCH(0, 0);
    // zero pad columns j=10..15 in both buffers (never written by cp.async)
    for (int p = tid; p < 2 * EE * CH * 6; p += 128) {
        int bf = p / (EE * CH * 6);
        int r  = p - bf * (EE * CH * 6);
        int pe = r / (CH * 6);
        int r2 = r - pe * (CH * 6);
        int t  = r2 / 6;
        int jj = 10 + (r2 - t * 6);
        x_sh[bf][pe * ESTR + t * XPAD + jj] = 0.0f;
    }
    asm volatile("cp.async.wait_group 0;");
    __syncthreads();

    // ---- recurrence ----
    for (int cix = 0; cix < NCH; cix++) {
        if (cix + 1 < NCH) { PREFETCH(cix + 1, (cix + 1) & 1); }
        const float* xc = x_sh[cix & 1];

        for (int tt = 0; tt < CH; tt++) {
            // h fragments: 4 conflict-free LDS.128
            uint4 hf[4];
            #pragma unroll
            for (int kc = 0; kc < 4; kc++) hf[kc] = hfrag_sh[kc][lane];

            // x fragments: tf32-hi only (4 conflict-free LDS.32 + 4 cvt)
            const float* xe = xc + gid * ESTR + tt * XPAD;
            uu bxh[4];
            #pragma unroll
            for (int kc = 0; kc < 2; kc++) {
                bxh[2 * kc]     = tf32r(xe[8 * kc + tig]);
                bxh[2 * kc + 1] = tf32r(xe[8 * kc + tig + 4]);
            }

            #pragma unroll
            for (int mt = 0; mt < 2; mt++) {
                // chain A: W_hi * b_hi (+ x), bias pre-loaded
                float ca0 = bv[mt][0], ca1 = bv[mt][0];
                float ca2 = bv[mt][1], ca3 = bv[mt][1];
                // chain B: W_hi * h_lo (independent)
                float cb0 = 0.f, cb1 = 0.f, cb2 = 0.f, cb3 = 0.f;

                #pragma unroll
                for (int kc = 0; kc < 4; kc++) {
                    mma8(ca0, ca1, ca2, ca3,
                         ah[mt][kc][0], ah[mt][kc][1], ah[mt][kc][2], ah[mt][kc][3],
                         hf[kc].x, hf[kc].z);
                    mma8(cb0, cb1, cb2, cb3,
                         ah[mt][kc][0], ah[mt][kc][1], ah[mt][kc][2], ah[mt][kc][3],
                         hf[kc].y, hf[kc].w);
                }
                #pragma unroll
                for (int kc = 0; kc < 2; kc++) {
                    mma8(ca0, ca1, ca2, ca3,
                         ax[mt][kc][0], ax[mt][kc][1], ax[mt][kc][2], ax[mt][kc][3],
                         bxh[2 * kc], bxh[2 * kc + 1]);
                }

                float d0 = ca0 + cb0, d1 = ca1 + cb1;
                float d2 = ca2 + cb2, d3 = ca3 + cb3;
                float a0v = fmaf(alpha, tanha(d0), beta);
                float a1v = fmaf(alpha, tanha(d1), beta);
                float a2v = fmaf(alpha, tanha(d2), beta);
                float a3v = fmaf(alpha, tanha(d3), beta);
                // rows gid / gid+8 within m-tile; cols (elems) 2tig, 2tig+1
                *reinterpret_cast<float2*>(&gates_sh[w][16 * mt + gid][2 * tig]) =
                    make_float2(a0v, a1v);
                *reinterpret_cast<float2*>(&gates_sh[w][16 * mt + 8 + gid][2 * tig]) =
                    make_float2(a2v, a3v);
            }
            __syncthreads();   // bar1: gates ready; all h reads complete

            // elementwise update: states (l, e) and (l+16, e)
            {
                float iv = gates_sh[0][l][e],      fv = gates_sh[1][l][e];
                float gv = gates_sh[2][l][e],      ov = gates_sh[3][l][e];
                c_a = fmaf(fv, c_a, iv * gv);
                h_a = ov * tanha(c_a);
                uu p = tf32r(h_a);
                *hwA = make_uint2(p, __float_as_uint(h_a - __uint_as_float(p)));

                float iv2 = gates_sh[0][l + 16][e], fv2 = gates_sh[1][l + 16][e];
                float gv2 = gates_sh[2][l + 16][e], ov2 = gates_sh[3][l + 16][e];
                c_b = fmaf(fv2, c_b, iv2 * gv2);
                h_b = ov2 * tanha(c_b);
                uu p2 = tf32r(h_b);
                *hwB = make_uint2(p2, __float_as_uint(h_b - __uint_as_float(p2)));
            }
            __syncthreads();   // bar2: new h visible
        }
        asm volatile("cp.async.wait_group 0;");
        __syncthreads();
    }

    // ---- final linear head ----
    float* scratch = &gates_sh[0][0][0];      // reuse as [EE][16]
    scratch[e * 16 + l] = fmaf(h_a, wl0, h_b * wl1);
    __syncthreads();
    if (tid < EE) {
        float sum = b_lin[0];
        #pragma unroll
        for (int q = 0; q < 16; q++) sum += scratch[tid * 16 + q];
        out[base + tid] = sum;
    }
}

extern "C" void kernel_launch(void* const* d_in, const int* in_sizes, int n_in,
                              void* d_out, int out_size) {
    const float* x     = (const float*)d_in[0];
    const float* h0    = (const float*)d_in[1];
    const float* c0    = (const float*)d_in[2];
    const float* W_ih  = (const float*)d_in[3];
    const float* W_hh  = (const float*)d_in[4];
    const float* b_ih  = (const float*)d_in[5];
    const float* b_hh  = (const float*)d_in[6];
    const float* W_lin = (const float*)d_in[7];
    const float* b_lin = (const float*)d_in[8];
    float* out = (float*)d_out;

    int B = in_sizes[1] / HH;   // 4096
    lstm_kernel<<<B / EE, 128>>>(x, h0, c0, W_ih, W_hh, b_ih, b_hh, W_lin, b_lin, out);
}